// round 7
// baseline (speedup 1.0000x reference)
#include <cuda_runtime.h>

#define NB 512      // batch
#define NT 1024     // time steps
#define HID 64      // hidden
#define NG 192      // 3 * HID gates
#define NTH 768     // threads: A = 0..383 (hidden dot), B = 384..767 (input dot)

// Scratch (static __device__ arrays; allocation-free per harness rules)
__device__ float g_h0[(size_t)NT * NB * HID];  // [t][b][j] layer outputs (ping)
__device__ float g_h1[(size_t)NT * NB * HID];  // (pong)

__device__ __forceinline__ float sigf(float x) {
    return __fdividef(1.f, 1.f + __expf(-x));
}
__device__ __forceinline__ float tanh_(float x) {
    return fmaf(2.f, sigf(2.f * x), -1.f);
}

// packed fp32x2 ops
__device__ __forceinline__ unsigned long long ffma2(unsigned long long a,
                                                    unsigned long long b,
                                                    unsigned long long c) {
    unsigned long long d;
    asm("fma.rn.f32x2 %0, %1, %2, %3;" : "=l"(d) : "l"(a), "l"(b), "l"(c));
    return d;
}
__device__ __forceinline__ unsigned long long fadd2(unsigned long long a,
                                                    unsigned long long b) {
    unsigned long long d;
    asm("add.rn.f32x2 %0, %1, %2;" : "=l"(d) : "l"(a), "l"(b));
    return d;
}
__device__ __forceinline__ float f2sum(unsigned long long v) {
    return __uint_as_float((unsigned)v) + __uint_as_float((unsigned)(v >> 32));
}

// Half-dot over 4 rows, K split across a LANE PAIR in interleaved 16B chunks:
// lane kh reads chunks {2k+kh}, k=0..7. Combine halves via shfl.bfly(1).
// s[r] = full (un-biased) dot of w-row with buf row r.
__device__ __forceinline__ void dot4h(const unsigned long long* __restrict__ w2,
                                      const float* __restrict__ buf,
                                      int stride, int kh, float* s) {
    unsigned long long acc[8];
#pragma unroll
    for (int i = 0; i < 8; i++) acc[i] = 0;
#pragma unroll
    for (int k = 0; k < 8; k++) {
        const int c = 2 * k + kh;    // interleaved 16B chunk index
#pragma unroll
        for (int r = 0; r < 4; r++) {
            ulonglong2 v = ((const ulonglong2*)(buf + r * stride))[c];
            acc[2 * r]     = ffma2(w2[2 * k],     v.x, acc[2 * r]);
            acc[2 * r + 1] = ffma2(w2[2 * k + 1], v.y, acc[2 * r + 1]);
        }
    }
#pragma unroll
    for (int r = 0; r < 4; r++) {
        float half = f2sum(fadd2(acc[2 * r], acc[2 * r + 1]));
        s[r] = half + __shfl_xor_sync(0xFFFFFFFFu, half, 1);
    }
}

// ---------------------------------------------------------------------------
// Fused GRU layer. 128 blocks x 768 threads; block owns 4 batch rows.
// A (0..383): hidden dot, lane-pair per gate (g = idx>>1, kh = idx&1).
//   g<128 -> r/z sigmoids (rows split by kh); g>=128 -> publish shh.
// B (384..767): input dot for t+1 (same lane-pair scheme) + x prefetch with a
//   full-iteration register distance. 256 threads do the h update (1 elt each).
// Gate order (torch): r=[0:64), z=[64:128), n=[128:192).
// L0: input dim 5, x is [B][T][5]; else input = previous h, [T][B][64].
// ---------------------------------------------------------------------------
template <int L0>
__global__ __launch_bounds__(NTH, 1)
void k_fscan(const float* __restrict__ xin,
             const float* __restrict__ w_ih, const float* __restrict__ b_ih,
             const float* __restrict__ w_hh, const float* __restrict__ b_hh,
             float* __restrict__ hout, int store_all) {
    const int tid = threadIdx.x;
    const int b0 = blockIdx.x * 4;
    const bool isA = tid < 384;
    const int idx = isA ? tid : tid - 384;   // FIX: 384 is not a pow2; no & mask
    const int g = idx >> 1;          // gate 0..191
    const int kh = idx & 1;          // K half (lane pair)
    const int ra = kh * 2;           // tail rows for this thread: ra, ra+1

    __shared__ __align__(16) float h_sh[4][68];        // padded, 16B-aligned rows
    __shared__ __align__(16) float x_sh[2][4][HID];    // L0 uses cols < 5
    __shared__ float sih_sh[2][4][193];                // input-side preacts (padded)
    __shared__ float rz_sh[2][4][65];                  // [r|z][row][j] (padded)
    __shared__ float shh_sh[4][65];                    // hidden preact, n gates

    // ---- weights into registers: 8 interleaved 16B chunks (32 floats) ----
    unsigned long long w2[16];
    float w5[5];
    float bias;
    if (isA) {
        const ulonglong2* wp = (const ulonglong2*)(w_hh + (size_t)g * HID);
#pragma unroll
        for (int k = 0; k < 8; k++) {
            ulonglong2 v = wp[2 * k + kh];
            w2[2 * k] = v.x; w2[2 * k + 1] = v.y;
        }
        bias = b_hh[g];
    } else {
        if (L0) {
#pragma unroll
            for (int c = 0; c < 5; c++) w5[c] = w_ih[g * 5 + c];
        } else {
            const ulonglong2* wp = (const ulonglong2*)(w_ih + (size_t)g * HID);
#pragma unroll
            for (int k = 0; k < 8; k++) {
                ulonglong2 v = wp[2 * k + kh];
                w2[2 * k] = v.x; w2[2 * k + 1] = v.y;
            }
        }
        bias = b_ih[g];
    }

    for (int i = tid; i < 4 * 68; i += NTH) ((float*)h_sh)[i] = 0.f;

    // ---- prologue: x(0) -> x_sh[1], x(1) -> x_sh[0] ----
    if (L0) {
        if (tid < 20) {
            int r = tid / 5, c = tid % 5;
            x_sh[1][r][c] = xin[(size_t)(b0 + r) * NT * 5 + c];
        } else if (tid < 40) {
            int u = tid - 20, r = u / 5, c = u % 5;
            x_sh[0][r][c] = xin[((size_t)(b0 + r) * NT + 1) * 5 + c];
        }
    } else {
        if (tid < 64) {
            ((float4*)&x_sh[1][0][0])[tid] =
                ((const float4*)(xin + (size_t)b0 * HID))[tid];
        } else if (tid < 128) {
            int u = tid - 64;
            ((float4*)&x_sh[0][0][0])[u] =
                ((const float4*)(xin + ((size_t)NB + b0) * HID))[u];
        }
    }
    __syncthreads();

    // ---- prologue: sih(0) -> sih_sh[0] (B); prefetch reg <- x(2) ----
    float4 pf4 = make_float4(0.f, 0.f, 0.f, 0.f);
    float pf0 = 0.f;
    if (!isA) {
        if (L0) {
#pragma unroll
            for (int rr = 0; rr < 2; rr++) {
                int r = ra + rr;
                float acc = bias;
#pragma unroll
                for (int c = 0; c < 5; c++) acc += w5[c] * x_sh[1][r][c];
                sih_sh[0][r][g] = acc;
            }
            if (idx < 20)
                pf0 = xin[((size_t)(b0 + idx / 5) * NT + 2) * 5 + idx % 5];
        } else {
            float s[4];
            dot4h(w2, &x_sh[1][0][0], HID, kh, s);
            sih_sh[0][ra][g] = bias + s[ra];
            sih_sh[0][ra + 1][g] = bias + s[ra + 1];
            if (idx < 64)
                pf4 = ((const float4*)(xin + ((size_t)2 * NB + b0) * HID))[idx];
        }
    }
    __syncthreads();

    for (int t = 0; t < NT; t++) {
        const int p = t & 1;

        if (isA) {
            // ---- hidden dot ----
            float s[4];
            dot4h(w2, &h_sh[0][0], 68, kh, s);
            if (g < 128) {
                const int which = g >> 6;  // 0 = r, 1 = z
                const int j = g & 63;
                rz_sh[which][ra][j]     = sigf(sih_sh[p][ra][g] + bias + s[ra]);
                rz_sh[which][ra + 1][j] = sigf(sih_sh[p][ra + 1][g] + bias + s[ra + 1]);
            } else {
                const int j = g - 128;
                shh_sh[ra][j]     = bias + s[ra];
                shh_sh[ra + 1][j] = bias + s[ra + 1];
            }
        } else {
            // ---- stage x(t+2) from reg (loaded last iter), load x(t+3) ----
            if (L0) {
                if (idx < 20) {
                    if (t + 2 < NT) x_sh[p ^ 1][idx / 5][idx % 5] = pf0;
                    if (t + 3 < NT)
                        pf0 = xin[((size_t)(b0 + idx / 5) * NT + (t + 3)) * 5 + idx % 5];
                }
            } else {
                if (idx < 64) {
                    if (t + 2 < NT) ((float4*)&x_sh[p ^ 1][0][0])[idx] = pf4;
                    if (t + 3 < NT)
                        pf4 = ((const float4*)(xin + ((size_t)(t + 3) * NB + b0) * HID))[idx];
                }
            }
            // ---- input dot for t+1 (x_sh[p] holds x(t+1)) ----
            if (t + 1 < NT) {
                if (L0) {
#pragma unroll
                    for (int rr = 0; rr < 2; rr++) {
                        int r = ra + rr;
                        float acc = bias;
#pragma unroll
                        for (int c = 0; c < 5; c++) acc += w5[c] * x_sh[p][r][c];
                        sih_sh[p ^ 1][r][g] = acc;
                    }
                } else {
                    float s[4];
                    dot4h(w2, &x_sh[p][0][0], HID, kh, s);
                    sih_sh[p ^ 1][ra][g] = bias + s[ra];
                    sih_sh[p ^ 1][ra + 1][g] = bias + s[ra + 1];
                }
            }
        }
        __syncthreads();   // rz + shh + (staged x, sih(t+1)) published; h reads done

        // ---- h update: 256 threads, one (row, j) element each ----
        if (tid < 256) {
            const int r = tid >> 6, j = tid & 63;
            float sh = shh_sh[r][j];
            float n = tanh_(sih_sh[p][r][128 + j] + rz_sh[0][r][j] * sh);
            float z = rz_sh[1][r][j];
            float hp = h_sh[r][j];
            float hn = n + z * (hp - n);
            h_sh[r][j] = hn;
            if (store_all || t == NT - 1)
                hout[((size_t)t * NB + b0 + r) * HID + j] = hn;
        }
        __syncthreads();   // h_sh updated for next step
    }
}

// ---------------------------------------------------------------------------
// Final FC on last timestep: out[b] = h[T-1][b][:] . w_fc + b_fc
// ---------------------------------------------------------------------------
__global__ void k_fc(const float* __restrict__ hin,
                     const float* __restrict__ w_fc,
                     const float* __restrict__ b_fc,
                     float* __restrict__ out) {
    int b = blockIdx.x * blockDim.x + threadIdx.x;
    if (b >= NB) return;
    const float* hp = hin + ((size_t)(NT - 1) * NB + b) * HID;
    float acc = b_fc[0];
#pragma unroll
    for (int k = 0; k < HID; k++) acc += hp[k] * w_fc[k];
    out[b] = acc;
}

// ---------------------------------------------------------------------------
extern "C" void kernel_launch(void* const* d_in, const int* in_sizes, int n_in,
                              void* d_out, int out_size) {
    const float* x     = (const float*)d_in[0];
    const float* w_ih0 = (const float*)d_in[1];
    const float* w_hh0 = (const float*)d_in[2];
    const float* b_ih0 = (const float*)d_in[3];
    const float* b_hh0 = (const float*)d_in[4];
    const float* w_ih  = (const float*)d_in[5];   // [4][192][64]
    const float* w_hh  = (const float*)d_in[6];   // [4][192][64]
    const float* b_ih  = (const float*)d_in[7];   // [4][192]
    const float* b_hh  = (const float*)d_in[8];   // [4][192]
    const float* w_fc  = (const float*)d_in[9];
    const float* b_fc  = (const float*)d_in[10];
    float* out = (float*)d_out;

    float *hA = nullptr, *hB = nullptr;
    cudaGetSymbolAddress((void**)&hA, g_h0);
    cudaGetSymbolAddress((void**)&hB, g_h1);

    // Layer 0 (input dim 5), fused
    k_fscan<1><<<NB / 4, NTH>>>(x, w_ih0, b_ih0, w_hh0, b_hh0, hA, 1);

    // Layers 1..4, fused
    float* hin = hA;
    float* hou = hB;
    for (int L = 0; L < 4; L++) {
        int last = (L == 3);
        k_fscan<0><<<NB / 4, NTH>>>(hin,
                                    w_ih + (size_t)L * NG * HID, b_ih + L * NG,
                                    w_hh + (size_t)L * NG * HID, b_hh + L * NG,
                                    hou, !last);
        float* tmp = hin; hin = hou; hou = tmp;
    }

    // FC head on last timestep (hin holds the last layer's output)
    k_fc<<<2, 256>>>(hin, w_fc, b_fc, out);
}

// round 8
// speedup vs baseline: 1.1678x; 1.1678x over previous
#include <cuda_runtime.h>

#define NB 512      // batch
#define NT 1024     // time steps
#define HID 64      // hidden
#define NG 192      // 3 * HID gates

// Scratch (static __device__ arrays; allocation-free per harness rules)
__device__ float g_xg[(size_t)NT * NB * NG];   // [t][b][g] input-side gate preacts
__device__ float g_h0[(size_t)NT * NB * HID];  // [t][b][j] layer outputs (ping)
__device__ float g_h1[(size_t)NT * NB * HID];  // (pong)

__device__ __forceinline__ float sigf(float x) {
    return __fdividef(1.f, 1.f + __expf(-x));
}
__device__ __forceinline__ float tanh_(float x) {
    return fmaf(2.f, sigf(2.f * x), -1.f);
}

// packed fp32x2 ops
__device__ __forceinline__ unsigned long long ffma2(unsigned long long a,
                                                    unsigned long long b,
                                                    unsigned long long c) {
    unsigned long long d;
    asm("fma.rn.f32x2 %0, %1, %2, %3;" : "=l"(d) : "l"(a), "l"(b), "l"(c));
    return d;
}
__device__ __forceinline__ unsigned long long fadd2(unsigned long long a,
                                                    unsigned long long b) {
    unsigned long long d;
    asm("add.rn.f32x2 %0, %1, %2;" : "=l"(d) : "l"(a), "l"(b));
    return d;
}
__device__ __forceinline__ float f2sum(unsigned long long v) {
    return __uint_as_float((unsigned)v) + __uint_as_float((unsigned)(v >> 32));
}

// ---------------------------------------------------------------------------
// Layer-0 input GEMM: xg[t][b][g] = b0[g] + sum_{i<5} x[b][t][i] * w0[g][i]
// ---------------------------------------------------------------------------
__global__ void k_inp0(const float* __restrict__ x,
                       const float* __restrict__ w0,
                       const float* __restrict__ b0) {
    const int g = threadIdx.x;                 // 0..191
    const int row0 = blockIdx.x * 32;          // row = t*NB + b
    __shared__ float xs[32][5];

    float w[5];
#pragma unroll
    for (int i = 0; i < 5; i++) w[i] = w0[g * 5 + i];
    const float bias = b0[g];

    for (int i = g; i < 32 * 5; i += NG) {
        int r = i / 5, c = i % 5;
        int row = row0 + r;
        int t = row / NB, b = row % NB;        // xg rows are t-major
        xs[r][c] = x[((size_t)b * NT + t) * 5 + c];
    }
    __syncthreads();

#pragma unroll 4
    for (int r = 0; r < 32; r++) {
        float acc = bias;
#pragma unroll
        for (int c = 0; c < 5; c++) acc += w[c] * xs[r][c];
        g_xg[((size_t)(row0 + r)) * NG + g] = acc;
    }
}

// ---------------------------------------------------------------------------
// Layers 1..4 input GEMM: 64 rows/block, 8-row register blocking, f32x2 FMA.
// Thread g owns gate g's 64-weight row in registers. All LDS broadcast.
// ---------------------------------------------------------------------------
__global__ __launch_bounds__(192, 2)
void k_inp(const float* __restrict__ hin,
           const float* __restrict__ w_ih,
           const float* __restrict__ b_ih) {
    const int g = threadIdx.x;
    const size_t row0 = (size_t)blockIdx.x * 64;
    __shared__ __align__(16) float hs[64][HID];

    unsigned long long w2[32];
    const ulonglong2* wp = (const ulonglong2*)(w_ih + (size_t)g * HID);
#pragma unroll
    for (int k = 0; k < 16; k++) {
        ulonglong2 v = wp[k];
        w2[2 * k] = v.x; w2[2 * k + 1] = v.y;
    }
    const float bias = b_ih[g];

    // 64 rows x 64 floats = 1024 float4
    const float4* src = (const float4*)(hin + row0 * HID);
    float4* dst = (float4*)hs;
    for (int i = g; i < 1024; i += NG) dst[i] = src[i];
    __syncthreads();

#pragma unroll 1
    for (int grp = 0; grp < 8; grp++) {
        const int base = grp * 8;
        unsigned long long ax[8], ay[8];
#pragma unroll
        for (int i = 0; i < 8; i++) { ax[i] = 0; ay[i] = 0; }
#pragma unroll
        for (int k = 0; k < 16; k++) {
#pragma unroll
            for (int i = 0; i < 8; i++) {
                ulonglong2 v = ((const ulonglong2*)hs[base + i])[k];
                ax[i] = ffma2(w2[2 * k],     v.x, ax[i]);
                ay[i] = ffma2(w2[2 * k + 1], v.y, ay[i]);
            }
        }
#pragma unroll
        for (int i = 0; i < 8; i++)
            g_xg[(row0 + base + i) * NG + g] = bias + f2sum(fadd2(ax[i], ay[i]));
    }
}

// ---------------------------------------------------------------------------
// Recurrent scan, 3-gates-per-thread. 256 blocks x 128 threads, 2 CTAs/SM.
// Thread (j, r): owns w_hh rows j (r-gate), 64+j (z), 128+j (n) in registers,
// computes all three dots for batch row r, then updates h[j] locally.
// Double-buffered h in smem -> ONE barrier per step. h_prev kept in register.
// Gate order (torch): r=[0:64), z=[64:128), n=[128:192).
// ---------------------------------------------------------------------------
__global__ __launch_bounds__(128, 2)
void k_scan(const float* __restrict__ w_hh,
            const float* __restrict__ b_hh,
            float* __restrict__ hout, int store_all) {
    const int tid = threadIdx.x;
    const int j = tid & 63;
    const int r = tid >> 6;                 // row within block (0/1)
    const int b = blockIdx.x * 2 + r;       // global batch row

    __shared__ __align__(16) float h_sh[2][2][72];   // [phase][row][j, padded]

    // three weight rows in registers (96 x f32x2)
    unsigned long long wr[32], wz[32], wn[32];
    {
        const ulonglong2* pr = (const ulonglong2*)(w_hh + (size_t)j * HID);
        const ulonglong2* pz = (const ulonglong2*)(w_hh + (size_t)(64 + j) * HID);
        const ulonglong2* pn = (const ulonglong2*)(w_hh + (size_t)(128 + j) * HID);
#pragma unroll
        for (int k = 0; k < 16; k++) {
            ulonglong2 vr = pr[k], vz = pz[k], vn = pn[k];
            wr[2 * k] = vr.x; wr[2 * k + 1] = vr.y;
            wz[2 * k] = vz.x; wz[2 * k + 1] = vz.y;
            wn[2 * k] = vn.x; wn[2 * k + 1] = vn.y;
        }
    }
    const float br = b_hh[j], bz = b_hh[64 + j], bn = b_hh[128 + j];

    h_sh[0][r][j] = 0.f;
    h_sh[1][r][j] = 0.f;
    float hprev = 0.f;
    __syncthreads();

    // xg pointers: row (t*NB + b), gates j / 64+j / 128+j
    const float* xp = g_xg + (size_t)b * NG + j;
    float xr = xp[0], xz = xp[64], xn = xp[128];

    for (int t = 0; t < NT; t++) {
        // prefetch next step's xg
        float pxr = 0.f, pxz = 0.f, pxn = 0.f;
        if (t + 1 < NT) {
            const float* q = g_xg + ((size_t)(t + 1) * NB + b) * NG + j;
            pxr = q[0]; pxz = q[64]; pxn = q[128];
        }

        const int p = t & 1;
        unsigned long long ar0 = 0, ar1 = 0, az0 = 0, az1 = 0, an0 = 0, an1 = 0;
        const ulonglong2* hv = (const ulonglong2*)h_sh[p][r];
#pragma unroll
        for (int k = 0; k < 16; k++) {
            ulonglong2 v = hv[k];                       // broadcast LDS.128
            ar0 = ffma2(wr[2 * k], v.x, ar0); ar1 = ffma2(wr[2 * k + 1], v.y, ar1);
            az0 = ffma2(wz[2 * k], v.x, az0); az1 = ffma2(wz[2 * k + 1], v.y, az1);
            an0 = ffma2(wn[2 * k], v.x, an0); an1 = ffma2(wn[2 * k + 1], v.y, an1);
        }
        float sr = br + f2sum(fadd2(ar0, ar1));
        float sz = bz + f2sum(fadd2(az0, az1));
        float sn = bn + f2sum(fadd2(an0, an1));

        float rg = sigf(xr + sr);
        float zg = sigf(xz + sz);
        float ng = tanh_(xn + rg * sn);
        float hn = ng + zg * (hprev - ng);

        h_sh[p ^ 1][r][j] = hn;                          // write next phase buf
        if (store_all || t == NT - 1)
            hout[((size_t)t * NB + b) * HID + j] = hn;
        hprev = hn;
        __syncthreads();                                 // single barrier/step

        xr = pxr; xz = pxz; xn = pxn;
    }
}

// ---------------------------------------------------------------------------
// Final FC on last timestep: out[b] = h[T-1][b][:] . w_fc + b_fc
// ---------------------------------------------------------------------------
__global__ void k_fc(const float* __restrict__ hin,
                     const float* __restrict__ w_fc,
                     const float* __restrict__ b_fc,
                     float* __restrict__ out) {
    int b = blockIdx.x * blockDim.x + threadIdx.x;
    if (b >= NB) return;
    const float* hp = hin + ((size_t)(NT - 1) * NB + b) * HID;
    float acc = b_fc[0];
#pragma unroll
    for (int k = 0; k < HID; k++) acc += hp[k] * w_fc[k];
    out[b] = acc;
}

// ---------------------------------------------------------------------------
extern "C" void kernel_launch(void* const* d_in, const int* in_sizes, int n_in,
                              void* d_out, int out_size) {
    const float* x     = (const float*)d_in[0];
    const float* w_ih0 = (const float*)d_in[1];
    const float* w_hh0 = (const float*)d_in[2];
    const float* b_ih0 = (const float*)d_in[3];
    const float* b_hh0 = (const float*)d_in[4];
    const float* w_ih  = (const float*)d_in[5];   // [4][192][64]
    const float* w_hh  = (const float*)d_in[6];   // [4][192][64]
    const float* b_ih  = (const float*)d_in[7];   // [4][192]
    const float* b_hh  = (const float*)d_in[8];   // [4][192]
    const float* w_fc  = (const float*)d_in[9];
    const float* b_fc  = (const float*)d_in[10];
    float* out = (float*)d_out;

    float *hA = nullptr, *hB = nullptr;
    cudaGetSymbolAddress((void**)&hA, g_h0);
    cudaGetSymbolAddress((void**)&hB, g_h1);

    // Layer 0 (input dim 5)
    k_inp0<<<(NT * NB) / 32, NG>>>(x, w_ih0, b_ih0);
    k_scan<<<NB / 2, 128>>>(w_hh0, b_hh0, hA, 1);

    // Layers 1..4
    float* hin = hA;
    float* hou = hB;
    for (int L = 0; L < 4; L++) {
        int last = (L == 3);
        k_inp<<<(NT * NB) / 64, NG>>>(hin, w_ih + (size_t)L * NG * HID, b_ih + L * NG);
        k_scan<<<NB / 2, 128>>>(w_hh + (size_t)L * NG * HID, b_hh + L * NG, hou, !last);
        float* tmp = hin; hin = hou; hou = tmp;
    }

    // FC head on last timestep (hin holds the last layer's output)
    k_fc<<<2, 256>>>(hin, w_fc, b_fc, out);
}

// round 9
// speedup vs baseline: 1.2505x; 1.0708x over previous
#include <cuda_runtime.h>

#define NB 512      // batch
#define NT 1024     // time steps
#define HID 64      // hidden
#define NG 192      // 3 * HID gates
#define NC 8        // chunks
#define CS (NT / NC)  // 128 steps per chunk

// Scratch (static __device__ arrays; allocation-free per harness rules)
__device__ float g_xgA[(size_t)NT * NB * NG];  // xg for even layers (0,2,4)
__device__ float g_xgB[(size_t)NT * NB * NG];  // xg for odd layers (1,3)
__device__ float g_h0[(size_t)NT * NB * HID];  // layer outputs ping (L0,2,4 out)
__device__ float g_h1[(size_t)NT * NB * HID];  // pong (L1,3 out)
__device__ float g_state[NB * HID];            // scan h state across chunks

__device__ __forceinline__ float sigf(float x) {
    return __fdividef(1.f, 1.f + __expf(-x));
}
__device__ __forceinline__ float tanh_(float x) {
    return fmaf(2.f, sigf(2.f * x), -1.f);
}

// packed fp32x2 ops
__device__ __forceinline__ unsigned long long ffma2(unsigned long long a,
                                                    unsigned long long b,
                                                    unsigned long long c) {
    unsigned long long d;
    asm("fma.rn.f32x2 %0, %1, %2, %3;" : "=l"(d) : "l"(a), "l"(b), "l"(c));
    return d;
}
__device__ __forceinline__ unsigned long long fadd2(unsigned long long a,
                                                    unsigned long long b) {
    unsigned long long d;
    asm("add.rn.f32x2 %0, %1, %2;" : "=l"(d) : "l"(a), "l"(b));
    return d;
}
__device__ __forceinline__ float f2sum(unsigned long long v) {
    return __uint_as_float((unsigned)v) + __uint_as_float((unsigned)(v >> 32));
}

// ---------------------------------------------------------------------------
// Layer-0 input GEMM (full, upfront): xg[t][b][g] = b0[g] + x[b][t][:].w0[g][:]
// ---------------------------------------------------------------------------
__global__ void k_inp0(const float* __restrict__ x,
                       const float* __restrict__ w0,
                       const float* __restrict__ b0,
                       float* __restrict__ xg) {
    const int g = threadIdx.x;                 // 0..191
    const int row0 = blockIdx.x * 32;          // row = t*NB + b
    __shared__ float xs[32][5];

    float w[5];
#pragma unroll
    for (int i = 0; i < 5; i++) w[i] = w0[g * 5 + i];
    const float bias = b0[g];

    for (int i = g; i < 32 * 5; i += NG) {
        int r = i / 5, c = i % 5;
        int row = row0 + r;
        int t = row / NB, b = row % NB;        // xg rows are t-major
        xs[r][c] = x[((size_t)b * NT + t) * 5 + c];
    }
    __syncthreads();

#pragma unroll 4
    for (int r = 0; r < 32; r++) {
        float acc = bias;
#pragma unroll
        for (int c = 0; c < 5; c++) acc += w[c] * xs[r][c];
        xg[((size_t)(row0 + r)) * NG + g] = acc;
    }
}

// ---------------------------------------------------------------------------
// Layers 1..4 input GEMM, chunked: 64 rows/block, 8-row register blocking.
// ---------------------------------------------------------------------------
__global__ __launch_bounds__(192, 2)
void k_inp(const float* __restrict__ hin,
           const float* __restrict__ w_ih,
           const float* __restrict__ b_ih,
           float* __restrict__ xg, int row_base) {
    const int g = threadIdx.x;
    const size_t row0 = (size_t)row_base + (size_t)blockIdx.x * 64;
    __shared__ __align__(16) float hs[64][HID];

    unsigned long long w2[32];
    const ulonglong2* wp = (const ulonglong2*)(w_ih + (size_t)g * HID);
#pragma unroll
    for (int k = 0; k < 16; k++) {
        ulonglong2 v = wp[k];
        w2[2 * k] = v.x; w2[2 * k + 1] = v.y;
    }
    const float bias = b_ih[g];

    const float4* src = (const float4*)(hin + row0 * HID);
    float4* dst = (float4*)hs;
    for (int i = g; i < 1024; i += NG) dst[i] = src[i];
    __syncthreads();

#pragma unroll 1
    for (int grp = 0; grp < 8; grp++) {
        const int base = grp * 8;
        unsigned long long ax[8], ay[8];
#pragma unroll
        for (int i = 0; i < 8; i++) { ax[i] = 0; ay[i] = 0; }
#pragma unroll
        for (int k = 0; k < 16; k++) {
#pragma unroll
            for (int i = 0; i < 8; i++) {
                ulonglong2 v = ((const ulonglong2*)hs[base + i])[k];
                ax[i] = ffma2(w2[2 * k],     v.x, ax[i]);
                ay[i] = ffma2(w2[2 * k + 1], v.y, ay[i]);
            }
        }
#pragma unroll
        for (int i = 0; i < 8; i++)
            xg[(row0 + base + i) * NG + g] = bias + f2sum(fadd2(ax[i], ay[i]));
    }
}

// ---------------------------------------------------------------------------
// Recurrent scan, chunked (R2 structure): 256 blocks x 192 threads, 2 batch
// rows per block, 2 CTAs/SM. Thread g owns gate g's w_hh row in registers.
// State carried across chunk launches in g_state.
// Gate order (torch): r=[0:64), z=[64:128), n=[128:192).
// ---------------------------------------------------------------------------
__global__ __launch_bounds__(192, 2)
void k_scan(const float* __restrict__ w_hh,
            const float* __restrict__ b_hh,
            const float* __restrict__ xg,
            float* __restrict__ hout, int t0, int store_all) {
    const int g = threadIdx.x;
    const int b0 = blockIdx.x * 2;
    __shared__ __align__(16) float h_sh[2][HID];
    __shared__ float rz_sh[2][2][HID];   // [r|z][row][j]

    unsigned long long w2[32];
    const ulonglong2* wp = (const ulonglong2*)(w_hh + (size_t)g * HID);
#pragma unroll
    for (int k = 0; k < 16; k++) {
        ulonglong2 v = wp[k];
        w2[2 * k] = v.x; w2[2 * k + 1] = v.y;
    }
    const float bias = b_hh[g];

    if (g < 2 * HID) {
        const int row = g >> 6, j = g & 63;
        h_sh[row][j] = t0 ? g_state[(size_t)(b0 + row) * HID + j] : 0.f;
    }
    __syncthreads();

    const float* xb = xg + ((size_t)t0 * NB + b0) * NG + g;
    float xc0 = xb[0], xc1 = xb[NG];

    for (int t = t0; t < t0 + CS; t++) {
        // prefetch next step's xg (beyond-chunk read is discarded)
        float xn0 = 0.f, xn1 = 0.f;
        if (t + 1 < NT) {
            const float* p = xg + ((size_t)(t + 1) * NB + b0) * NG + g;
            xn0 = p[0]; xn1 = p[NG];
        }

        unsigned long long a00 = 0, a01 = 0, a10 = 0, a11 = 0;
        const ulonglong2* h0 = (const ulonglong2*)h_sh[0];
        const ulonglong2* h1 = (const ulonglong2*)h_sh[1];
#pragma unroll
        for (int k = 0; k < 16; k++) {
            ulonglong2 v0 = h0[k];
            ulonglong2 v1 = h1[k];
            a00 = ffma2(w2[2 * k],     v0.x, a00);
            a01 = ffma2(w2[2 * k + 1], v0.y, a01);
            a10 = ffma2(w2[2 * k],     v1.x, a10);
            a11 = ffma2(w2[2 * k + 1], v1.y, a11);
        }
        float s0 = bias + f2sum(a00) + f2sum(a01);
        float s1 = bias + f2sum(a10) + f2sum(a11);

        if (g < 128) {                       // r and z gates
            const int which = g >> 6;        // 0 = r, 1 = z
            const int j = g & 63;
            rz_sh[which][0][j] = sigf(xc0 + s0);
            rz_sh[which][1][j] = sigf(xc1 + s1);
        }
        __syncthreads();                     // rz ready; dot reads of h_sh done
        if (g >= 128) {                      // n gate + state update
            const int j = g - 128;
            float n0 = tanh_(xc0 + rz_sh[0][0][j] * s0);
            float z0 = rz_sh[1][0][j];
            float hn0 = n0 + z0 * (h_sh[0][j] - n0);
            h_sh[0][j] = hn0;

            float n1 = tanh_(xc1 + rz_sh[0][1][j] * s1);
            float z1 = rz_sh[1][1][j];
            float hn1 = n1 + z1 * (h_sh[1][j] - n1);
            h_sh[1][j] = hn1;

            if (store_all || t == NT - 1) {
                float* op = hout + ((size_t)t * NB + b0) * HID + j;
                op[0] = hn0;
                op[HID] = hn1;
            }
        }
        __syncthreads();                     // h_sh updated for next step
        xc0 = xn0; xc1 = xn1;
    }

    // persist state for the next chunk
    if (g < 2 * HID) {
        const int row = g >> 6, j = g & 63;
        g_state[(size_t)(b0 + row) * HID + j] = h_sh[row][j];
    }
}

// ---------------------------------------------------------------------------
// Final FC on last timestep: out[b] = h[T-1][b][:] . w_fc + b_fc
// ---------------------------------------------------------------------------
__global__ void k_fc(const float* __restrict__ hin,
                     const float* __restrict__ w_fc,
                     const float* __restrict__ b_fc,
                     float* __restrict__ out) {
    int b = blockIdx.x * blockDim.x + threadIdx.x;
    if (b >= NB) return;
    const float* hp = hin + ((size_t)(NT - 1) * NB + b) * HID;
    float acc = b_fc[0];
#pragma unroll
    for (int k = 0; k < HID; k++) acc += hp[k] * w_fc[k];
    out[b] = acc;
}

// ---------------------------------------------------------------------------
extern "C" void kernel_launch(void* const* d_in, const int* in_sizes, int n_in,
                              void* d_out, int out_size) {
    const float* x     = (const float*)d_in[0];
    const float* w_ih0 = (const float*)d_in[1];
    const float* w_hh0 = (const float*)d_in[2];
    const float* b_ih0 = (const float*)d_in[3];
    const float* b_hh0 = (const float*)d_in[4];
    const float* w_ih  = (const float*)d_in[5];   // [4][192][64]
    const float* w_hh  = (const float*)d_in[6];   // [4][192][64]
    const float* b_ih  = (const float*)d_in[7];   // [4][192]
    const float* b_hh  = (const float*)d_in[8];   // [4][192]
    const float* w_fc  = (const float*)d_in[9];
    const float* b_fc  = (const float*)d_in[10];
    float* out = (float*)d_out;

    float *hA, *hB, *xgA, *xgB;
    cudaGetSymbolAddress((void**)&hA, g_h0);
    cudaGetSymbolAddress((void**)&hB, g_h1);
    cudaGetSymbolAddress((void**)&xgA, g_xgA);
    cudaGetSymbolAddress((void**)&xgB, g_xgB);

    // side stream for the input GEMMs (leaked; created twice total)
    cudaStream_t gs;
    cudaStreamCreateWithFlags(&gs, cudaStreamNonBlocking);
    cudaEvent_t eS[4][NC], eI[4][NC];
    for (int l = 0; l < 4; l++)
        for (int c = 0; c < NC; c++) {
            cudaEventCreateWithFlags(&eS[l][c], cudaEventDisableTiming);
            cudaEventCreateWithFlags(&eI[l][c], cudaEventDisableTiming);
        }

    // Layer 0: full input GEMM, then chunked scans (all on capture stream)
    k_inp0<<<(NT * NB) / 32, NG>>>(x, w_ih0, b_ih0, xgA);
    for (int c = 0; c < NC; c++) {
        k_scan<<<NB / 2, NG>>>(w_hh0, b_hh0, xgA, hA, c * CS, 1);
        cudaEventRecord(eS[0][c], 0);
    }

    // Layers 1..4: GEMM chunks on side stream (pipelined one chunk behind the
    // producing scan), scan chunks on the capture stream.
    for (int L = 1; L <= 4; L++) {
        const float* wi = w_ih + (size_t)(L - 1) * NG * HID;
        const float* bi = b_ih + (L - 1) * NG;
        const float* wh = w_hh + (size_t)(L - 1) * NG * HID;
        const float* bh = b_hh + (L - 1) * NG;
        float* xg = (L & 1) ? xgB : xgA;
        const float* hin = (L & 1) ? hA : hB;   // hb[(L-1)&1]
        float* ho = (L & 1) ? hB : hA;          // hb[L&1]
        const int store_all = (L < 4);

        for (int c = 0; c < NC; c++) {
            cudaStreamWaitEvent(gs, eS[L - 1][c], 0);
            k_inp<<<(CS * NB) / 64, NG, 0, gs>>>(hin, wi, bi, xg, c * CS * NB);
            cudaEventRecord(eI[L - 1][c], gs);
        }
        for (int c = 0; c < NC; c++) {
            cudaStreamWaitEvent(0, eI[L - 1][c], 0);
            k_scan<<<NB / 2, NG>>>(wh, bh, xg, ho, c * CS, store_all);
            if (L < 4) cudaEventRecord(eS[L][c], 0);
        }
    }

    // FC head on last timestep (layer 4 output is in hA)
    k_fc<<<2, 256>>>(hA, w_fc, b_fc, out);
}

// round 11
// speedup vs baseline: 1.3409x; 1.0723x over previous
#include <cuda_runtime.h>

#define NB 512      // batch
#define NT 1024     // time steps
#define HID 64      // hidden
#define NG 192      // 3 * HID gates

// Scratch (static __device__ arrays; allocation-free per harness rules)
__device__ float g_xgA[(size_t)NT * NB * NG];  // xg for even layers (0,2,4)
__device__ float g_xgB[(size_t)NT * NB * NG];  // xg for odd layers (1,3)
__device__ float g_h0[(size_t)NT * NB * HID];  // layer outputs ping
__device__ float g_h1[(size_t)NT * NB * HID];  // pong

__device__ __forceinline__ float sigf(float x) {
    return __fdividef(1.f, 1.f + __expf(-x));
}
__device__ __forceinline__ float tanh_(float x) {
    return fmaf(2.f, sigf(2.f * x), -1.f);
}

// packed fp32x2 ops
__device__ __forceinline__ unsigned long long ffma2(unsigned long long a,
                                                    unsigned long long b,
                                                    unsigned long long c) {
    unsigned long long d;
    asm("fma.rn.f32x2 %0, %1, %2, %3;" : "=l"(d) : "l"(a), "l"(b), "l"(c));
    return d;
}
__device__ __forceinline__ unsigned long long fadd2(unsigned long long a,
                                                    unsigned long long b) {
    unsigned long long d;
    asm("add.rn.f32x2 %0, %1, %2;" : "=l"(d) : "l"(a), "l"(b));
    return d;
}
__device__ __forceinline__ float f2sum(unsigned long long v) {
    return __uint_as_float((unsigned)v) + __uint_as_float((unsigned)(v >> 32));
}

// ---------------------------------------------------------------------------
// Layer-0 input GEMM: xg[t][b][g] = b0[g] + x[b][t][:].w0[g][:]  (input dim 5)
// ---------------------------------------------------------------------------
__global__ void k_inp0(const float* __restrict__ x,
                       const float* __restrict__ w0,
                       const float* __restrict__ b0,
                       float* __restrict__ xg) {
    const int g = threadIdx.x;                 // 0..191
    const int row0 = blockIdx.x * 32;          // row = t*NB + b
    __shared__ float xs[32][5];

    float w[5];
#pragma unroll
    for (int i = 0; i < 5; i++) w[i] = w0[g * 5 + i];
    const float bias = b0[g];

    for (int i = g; i < 32 * 5; i += NG) {
        int r = i / 5, c = i % 5;
        int row = row0 + r;
        int t = row / NB, b = row % NB;        // xg rows are t-major
        xs[r][c] = x[((size_t)b * NT + t) * 5 + c];
    }
    __syncthreads();

#pragma unroll 4
    for (int r = 0; r < 32; r++) {
        float acc = bias;
#pragma unroll
        for (int c = 0; c < 5; c++) acc += w[c] * xs[r][c];
        xg[((size_t)(row0 + r)) * NG + g] = acc;
    }
}

// ---------------------------------------------------------------------------
// Layers 1..4 input GEMM, split-K over lane pairs. 384 threads, 64 rows/block.
// Thread (g = tid>>1, kh = tid&1) holds the kh-interleaved half of gate g's
// weight row (chunks 2k+kh). 4-row register blocking; shfl-combine halves.
// ---------------------------------------------------------------------------
__global__ __launch_bounds__(384, 2)
void k_inp(const float* __restrict__ hin,
           const float* __restrict__ w_ih,
           const float* __restrict__ b_ih,
           float* __restrict__ xg) {
    const int tid = threadIdx.x;
    const int g = tid >> 1;
    const int kh = tid & 1;
    const size_t row0 = (size_t)blockIdx.x * 64;
    __shared__ __align__(16) float hs[64][HID];

    unsigned long long w2[16];
    const ulonglong2* wp = (const ulonglong2*)(w_ih + (size_t)g * HID);
#pragma unroll
    for (int k = 0; k < 8; k++) {
        ulonglong2 v = wp[2 * k + kh];
        w2[2 * k] = v.x; w2[2 * k + 1] = v.y;
    }
    const float bias = b_ih[g];

    // 64 rows x 64 floats = 1024 float4
    const float4* src = (const float4*)(hin + row0 * HID);
    float4* dst = (float4*)hs;
    for (int i = tid; i < 1024; i += 384) dst[i] = src[i];
    __syncthreads();

#pragma unroll 1
    for (int grp = 0; grp < 16; grp++) {
        const int base = grp * 4;
        unsigned long long ax[4], ay[4];
#pragma unroll
        for (int i = 0; i < 4; i++) { ax[i] = 0; ay[i] = 0; }
#pragma unroll
        for (int k = 0; k < 8; k++) {
            const int c = 2 * k + kh;
#pragma unroll
            for (int i = 0; i < 4; i++) {
                ulonglong2 v = ((const ulonglong2*)hs[base + i])[c];
                ax[i] = ffma2(w2[2 * k],     v.x, ax[i]);
                ay[i] = ffma2(w2[2 * k + 1], v.y, ay[i]);
            }
        }
        float s[4];
#pragma unroll
        for (int i = 0; i < 4; i++) {
            float h = f2sum(fadd2(ax[i], ay[i]));
            s[i] = h + __shfl_xor_sync(0xFFFFFFFFu, h, 1);
        }
        // lane kh stores rows base+2kh, base+2kh+1
#pragma unroll
        for (int i = 0; i < 2; i++) {
            int r = base + 2 * kh + i;
            xg[(row0 + r) * NG + g] = bias + s[2 * kh + i];
        }
    }
}

// ---------------------------------------------------------------------------
// Recurrent scan, split-K over lane pairs. 256 blocks x 384 threads, 2 batch
// rows/block, 2 CTAs/SM (24 warps/SM). Thread (g, kh) holds half of gate g's
// w_hh row; lane kh owns batch row kh for gate I/O. r/z lanes publish sigmoids
// to smem; n lanes do the full h update themselves (no shh round-trip).
// Gate order (torch): r=[0:64), z=[64:128), n=[128:192).
// ---------------------------------------------------------------------------
__global__ __launch_bounds__(384, 2)
void k_scan(const float* __restrict__ w_hh,
            const float* __restrict__ b_hh,
            const float* __restrict__ xg,
            float* __restrict__ hout, int store_all) {
    const int tid = threadIdx.x;
    const int g = tid >> 1;          // gate 0..191
    const int kh = tid & 1;          // K half == owned batch row
    const int j = g & 63;
    const int b0 = blockIdx.x * 2;

    __shared__ __align__(16) float h_sh[2][HID];
    __shared__ float rz_sh[2][2][HID];   // [r|z][row][j]

    unsigned long long w2[16];
    const ulonglong2* wp = (const ulonglong2*)(w_hh + (size_t)g * HID);
#pragma unroll
    for (int k = 0; k < 8; k++) {
        ulonglong2 v = wp[2 * k + kh];
        w2[2 * k] = v.x; w2[2 * k + 1] = v.y;
    }
    const float bias = b_hh[g];

    if (tid < 2 * HID) ((float*)h_sh)[tid] = 0.f;
    __syncthreads();

    // this thread's xg element: row (b0+kh), gate g
    const float* xb = xg + ((size_t)b0 + kh) * NG + g;
    float xc = xb[0];

    for (int t = 0; t < NT; t++) {
        float xn = 0.f;
        if (t + 1 < NT) xn = xb[(size_t)(t + 1) * NB * NG];

        // half-dot for both batch rows
        unsigned long long a0x = 0, a0y = 0, a1x = 0, a1y = 0;
        const ulonglong2* h0 = (const ulonglong2*)h_sh[0];
        const ulonglong2* h1 = (const ulonglong2*)h_sh[1];
#pragma unroll
        for (int k = 0; k < 8; k++) {
            const int c = 2 * k + kh;
            ulonglong2 v0 = h0[c], v1 = h1[c];
            a0x = ffma2(w2[2 * k],     v0.x, a0x);
            a0y = ffma2(w2[2 * k + 1], v0.y, a0y);
            a1x = ffma2(w2[2 * k],     v1.x, a1x);
            a1y = ffma2(w2[2 * k + 1], v1.y, a1y);
        }
        float s0 = f2sum(fadd2(a0x, a0y));
        float s1 = f2sum(fadd2(a1x, a1y));
        s0 += __shfl_xor_sync(0xFFFFFFFFu, s0, 1);
        s1 += __shfl_xor_sync(0xFFFFFFFFu, s1, 1);
        // s for this lane's own row (kh): full hidden preact + bias
        const float sown = bias + (kh ? s1 : s0);

        if (g < 128) {
            // r/z gate for own row
            const int which = g >> 6;   // 0 = r, 1 = z
            rz_sh[which][kh][j] = sigf(xc + sown);
        }
        __syncthreads();                 // rz ready; dot reads of h_sh done

        if (g >= 128) {
            // n gate + full update for own row (this thread owns h_sh[kh][j])
            float n = tanh_(xc + rz_sh[0][kh][j] * sown);
            float z = rz_sh[1][kh][j];
            float hp = h_sh[kh][j];
            float hn = n + z * (hp - n);
            h_sh[kh][j] = hn;
            if (store_all || t == NT - 1)
                hout[((size_t)t * NB + b0 + kh) * HID + j] = hn;
        }
        __syncthreads();                 // h_sh updated for next step
        xc = xn;
    }
}

// ---------------------------------------------------------------------------
// Final FC on last timestep: out[b] = h[T-1][b][:] . w_fc + b_fc
// ---------------------------------------------------------------------------
__global__ void k_fc(const float* __restrict__ hin,
                     const float* __restrict__ w_fc,
                     const float* __restrict__ b_fc,
                     float* __restrict__ out) {
    int b = blockIdx.x * blockDim.x + threadIdx.x;
    if (b >= NB) return;
    const float* hp = hin + ((size_t)(NT - 1) * NB + b) * HID;
    float acc = b_fc[0];
#pragma unroll
    for (int k = 0; k < HID; k++) acc += hp[k] * w_fc[k];
    out[b] = acc;
}

// ---------------------------------------------------------------------------
extern "C" void kernel_launch(void* const* d_in, const int* in_sizes, int n_in,
                              void* d_out, int out_size) {
    const float* x     = (const float*)d_in[0];
    const float* w_ih0 = (const float*)d_in[1];
    const float* w_hh0 = (const float*)d_in[2];
    const float* b_ih0 = (const float*)d_in[3];
    const float* b_hh0 = (const float*)d_in[4];
    const float* w_ih  = (const float*)d_in[5];   // [4][192][64]
    const float* w_hh  = (const float*)d_in[6];   // [4][192][64]
    const float* b_ih  = (const float*)d_in[7];   // [4][192]
    const float* b_hh  = (const float*)d_in[8];   // [4][192]
    const float* w_fc  = (const float*)d_in[9];
    const float* b_fc  = (const float*)d_in[10];
    float* out = (float*)d_out;

    float *hA, *hB, *xgA, *xgB;
    cudaGetSymbolAddress((void**)&hA, g_h0);
    cudaGetSymbolAddress((void**)&hB, g_h1);
    cudaGetSymbolAddress((void**)&xgA, g_xgA);
    cudaGetSymbolAddress((void**)&xgB, g_xgB);

    // Layer 0
    k_inp0<<<(NT * NB) / 32, NG>>>(x, w_ih0, b_ih0, xgA);
    k_scan<<<NB / 2, 384>>>(w_hh0, b_hh0, xgA, hA, 1);

    // Layers 1..4 (serial; overlap was illusory at these occupancies)
    float* hin = hA;
    float* hou = hB;
    for (int L = 0; L < 4; L++) {
        int last = (L == 3);
        float* xg = (L & 1) ? xgA : xgB;
        k_inp<<<(NT * NB) / 64, 384>>>(hin, w_ih + (size_t)L * NG * HID,
                                       b_ih + L * NG, xg);
        k_scan<<<NB / 2, 384>>>(w_hh + (size_t)L * NG * HID, b_hh + L * NG,
                                xg, hou, !last);
        float* tmp = hin; hin = hou; hou = tmp;
    }

    // FC head on last timestep (hin holds the last layer's output)
    k_fc<<<2, 256>>>(hin, w_fc, b_fc, out);
}